// round 3
// baseline (speedup 1.0000x reference)
#include <cuda_runtime.h>

// Problem constants (from reference): T=2048, B=1024, H=50, 4H=200.
// Key insight: reference epilogue takes hs[:, -1, :] == batch index B-1 only,
// and the LSTM recurrence is independent per batch row. So we only need to
// run the LSTM for batch element 1023: a single length-2048 sequence, H=50.
#define TT 2048
#define BB 1024
#define HH 50
#define GG 200  // 4*H

// Scratch for per-timestep hidden state (output dot done in epilogue,
// off the sequential critical path). 2048*50*4 = 400 KB.
__device__ float g_hs[TT * HH];

__device__ __forceinline__ unsigned long long ffma2(unsigned long long a,
                                                    unsigned long long b,
                                                    unsigned long long c) {
    unsigned long long d;
    asm("fma.rn.f32x2 %0, %1, %2, %3;" : "=l"(d) : "l"(a), "l"(b), "l"(c));
    return d;
}

__device__ __forceinline__ float tanh_fast(float x) {
    float r;
    asm("tanh.approx.f32 %0, %1;" : "=f"(r) : "f"(x));
    return r;
}

__device__ __forceinline__ float sigmoid_fast(float x) {
    // 1/(1+exp(-x)) via ex2.approx + rcp.approx
    return __fdividef(1.0f, 1.0f + __expf(-x));
}

__global__ __launch_bounds__(256, 1)
void lstm_seq_kernel(const float* __restrict__ x,      // (T, B, 1)
                     const float* __restrict__ W_ih,   // (4H, 1)
                     const float* __restrict__ W_hh,   // (4H, H) row-major
                     const float* __restrict__ b_ih,   // (4H,)
                     const float* __restrict__ b_hh,   // (4H,)
                     const float* __restrict__ W_lin,  // (1, H)
                     const float* __restrict__ b_lin,  // (1,)
                     float* __restrict__ out)          // (T,1,1) -> T floats
{
    __shared__ __align__(8) float h_s[HH + 2];  // padded to even # of f32x2
    __shared__ float gact[GG];
    __shared__ float xcol[TT];

    const int j = threadIdx.x;

    // Preload x column for batch B-1 into shared.
    for (int t = j; t < TT; t += 256) xcol[t] = x[t * BB + (BB - 1)];
    if (j < HH + 2) h_s[j] = 0.0f;

    // Each gate-thread holds its W_hh row as 25 packed f32x2 registers.
    // Row byte offset = j*H*4 = j*200, always 8B-aligned.
    unsigned long long wp[25];
    float bsum = 0.0f, wih = 0.0f;
    if (j < GG) {
        const unsigned long long* wrow =
            reinterpret_cast<const unsigned long long*>(W_hh + j * HH);
        #pragma unroll
        for (int k = 0; k < 25; k++) wp[k] = wrow[k];
        bsum = b_ih[j] + b_hh[j];
        wih = W_ih[j];
    }
    float c = 0.0f;  // cell state for threads j < H
    __syncthreads();

    for (int t = 0; t < TT; t++) {
        if (j < GG) {
            // pre = bsum + x[t]*wih + dot(W_hh[j,:], h)
            unsigned long long acc0 = 0ull, acc1 = 0ull;
            const unsigned long long* h2 =
                reinterpret_cast<const unsigned long long*>(h_s);
            #pragma unroll
            for (int k = 0; k < 24; k += 2) {
                acc0 = ffma2(wp[k],     h2[k],     acc0);
                acc1 = ffma2(wp[k + 1], h2[k + 1], acc1);
            }
            acc0 = ffma2(wp[24], h2[24], acc0);
            union { unsigned long long u; float2 f; } u0, u1;
            u0.u = acc0; u1.u = acc1;
            float pre = bsum + xcol[t] * wih +
                        ((u0.f.x + u1.f.x) + (u0.f.y + u1.f.y));
            // gate order in rows: [0,50)=i  [50,100)=f  [100,150)=g  [150,200)=o
            float a = (j >= 2 * HH && j < 3 * HH) ? tanh_fast(pre)
                                                  : sigmoid_fast(pre);
            gact[j] = a;
        }
        __syncthreads();
        if (j < HH) {
            c = gact[HH + j] * c + gact[j] * gact[2 * HH + j];
            float hn = gact[3 * HH + j] * tanh_fast(c);
            h_s[j] = hn;
            g_hs[t * HH + j] = hn;  // fire-and-forget; consumed in epilogue
        }
        __syncthreads();
    }

    // Epilogue: out[t] = dot(h_t, W_lin) + b_lin, parallel over t.
    // __syncthreads above makes g_hs writes visible within the block.
    const float bl = b_lin[0];
    for (int t = j; t < TT; t += 256) {
        float s = bl;
        #pragma unroll
        for (int k = 0; k < HH; k++) s += g_hs[t * HH + k] * W_lin[k];
        out[t] = s;
    }
}

extern "C" void kernel_launch(void* const* d_in, const int* in_sizes, int n_in,
                              void* d_out, int out_size) {
    const float* x     = (const float*)d_in[0];
    const float* W_ih  = (const float*)d_in[1];
    const float* W_hh  = (const float*)d_in[2];
    const float* b_ih  = (const float*)d_in[3];
    const float* b_hh  = (const float*)d_in[4];
    const float* W_lin = (const float*)d_in[5];
    const float* b_lin = (const float*)d_in[6];
    lstm_seq_kernel<<<1, 256>>>(x, W_ih, W_hh, b_ih, b_hh, W_lin, b_lin,
                                (float*)d_out);
}

// round 6
// speedup vs baseline: 1.3742x; 1.3742x over previous
#include <cuda_runtime.h>

// T=2048, B=1024, H=50, 4H=200. Only batch row B-1 reaches the output
// (reference takes hs[:, -1, :] on the batch axis), and the recurrence is
// batch-independent -> single length-2048 sequence, H=50, on ONE SM.
#define TT 2048
#define BB 1024
#define HH 50
#define GG 200
#define NTHREADS 224  // 7 warps: covers 200 gate lanes, one fewer warp at barrier

// Per-timestep hidden history; output dot handled in parallel epilogue.
__device__ float g_hs[TT * HH];

typedef unsigned long long ull;

__device__ __forceinline__ ull ffma2(ull a, ull b, ull c) {
    ull d;
    asm("fma.rn.f32x2 %0, %1, %2, %3;" : "=l"(d) : "l"(a), "l"(b), "l"(c));
    return d;
}

__device__ __forceinline__ float tanh_fast(float x) {
    float r;
    asm("tanh.approx.f32 %0, %1;" : "=f"(r) : "f"(x));
    return r;
}

struct StepState {
    ull  wp[25];   // W_hh row, packed f32x2
    float bsum;    // b_ih + b_hh for this row
    float wih;     // W_ih for this row
    float asc;     // pre-scale for tanh arg  (1.0 for g-gate, 0.5 for sigmoid)
    float amul;    // post-mul               (1.0 / 0.5)
    float aadd;    // post-add               (0.0 / 0.5)
};

// One LSTM step: read h from hsrc, write new h to hdst. One barrier total.
__device__ __forceinline__ void lstm_step(
    const StepState& S, const float* __restrict__ hsrc,
    float* __restrict__ hdst, float xv, float& c,
    int lane, int g, int u, int t)
{
    // --- matvec: pre = bsum + x*wih + dot(W_hh[row,:], h) ---
    ull acc0 = 0ull, acc1 = 0ull;
    const ulonglong2* h4 = reinterpret_cast<const ulonglong2*>(hsrc);
    #pragma unroll
    for (int k = 0; k < 12; k++) {
        ulonglong2 p = h4[k];                 // LDS.128 broadcast
        acc0 = ffma2(S.wp[2 * k],     p.x, acc0);
        acc1 = ffma2(S.wp[2 * k + 1], p.y, acc1);
    }
    acc0 = ffma2(S.wp[24], reinterpret_cast<const ull*>(hsrc)[24], acc0);
    union { ull uv; float2 f; } u0, u1;
    u0.uv = acc0; u1.uv = acc1;
    float pre = fmaf(xv, S.wih, S.bsum) +
                ((u0.f.x + u1.f.x) + (u0.f.y + u1.f.y));

    // --- activation: tanh for g-gate, 0.5+0.5*tanh(x/2) == sigmoid ---
    float a = fmaf(tanh_fast(pre * S.asc), S.amul, S.aadd);

    // --- in-warp gate exchange: lanes 4u..4u+3 hold i,f,g,o of unit u ---
    int base = lane & ~3;
    float iv = __shfl_sync(0xffffffffu, a, base + 0, 32);
    float fv = __shfl_sync(0xffffffffu, a, base + 1, 32);
    float gv = __shfl_sync(0xffffffffu, a, base + 2, 32);
    float ov = __shfl_sync(0xffffffffu, a, base + 3, 32);

    // --- cell/hidden update (redundant in all 4 lanes, deterministic) ---
    c = fmaf(fv, c, iv * gv);
    float hn = ov * tanh_fast(c);
    if (g == 0 && u < HH) {
        hdst[u] = hn;
        g_hs[t * HH + u] = hn;   // fire-and-forget for the epilogue
    }
    __syncthreads();             // hdst visible before next step reads it
}

__global__ __launch_bounds__(NTHREADS, 1)
void lstm_seq_kernel(const float* __restrict__ x,      // (T, B, 1)
                     const float* __restrict__ W_ih,   // (4H, 1)
                     const float* __restrict__ W_hh,   // (4H, H)
                     const float* __restrict__ b_ih,
                     const float* __restrict__ b_hh,
                     const float* __restrict__ W_lin,  // (1, H)
                     const float* __restrict__ b_lin,
                     float* __restrict__ out)          // T floats
{
    __shared__ __align__(16) float h_s[2][56];  // double buffer, 16B aligned
    __shared__ float xcol[TT];

    const int j    = threadIdx.x;
    const int lane = j & 31;
    const int g    = j & 3;          // gate: 0=i 1=f 2=g(tanh) 3=o
    const int u    = j >> 2;         // hidden unit (0..55; >=50 redundant)
    const int uc   = (u < HH) ? u : (HH - 1);
    const int row  = g * HH + uc;    // row in the (4H, H) weight matrix

    for (int t = j; t < TT; t += NTHREADS) xcol[t] = x[t * BB + (BB - 1)];
    if (j < 56) { h_s[0][j] = 0.0f; h_s[1][j] = 0.0f; }

    StepState S;
    {
        const ull* wrow = reinterpret_cast<const ull*>(W_hh + row * HH);
        #pragma unroll
        for (int k = 0; k < 25; k++) S.wp[k] = wrow[k];
        S.bsum = b_ih[row] + b_hh[row];
        S.wih  = W_ih[row];
        bool is_tanh = (g == 2);
        S.asc  = is_tanh ? 1.0f : 0.5f;
        S.amul = is_tanh ? 1.0f : 0.5f;
        S.aadd = is_tanh ? 0.0f : 0.5f;
    }
    float c = 0.0f;
    __syncthreads();

    #pragma unroll 1
    for (int t = 0; t < TT; t += 2) {
        lstm_step(S, h_s[0], h_s[1], xcol[t],     c, lane, g, u, t);
        lstm_step(S, h_s[1], h_s[0], xcol[t + 1], c, lane, g, u, t + 1);
    }

    // Epilogue: out[t] = dot(h_t, W_lin) + b_lin, parallel over t.
    const float bl = b_lin[0];
    for (int t = j; t < TT; t += NTHREADS) {
        float s = bl;
        #pragma unroll
        for (int k = 0; k < HH; k++) s += g_hs[t * HH + k] * W_lin[k];
        out[t] = s;
    }
}

extern "C" void kernel_launch(void* const* d_in, const int* in_sizes, int n_in,
                              void* d_out, int out_size) {
    const float* x     = (const float*)d_in[0];
    const float* W_ih  = (const float*)d_in[1];
    const float* W_hh  = (const float*)d_in[2];
    const float* b_ih  = (const float*)d_in[3];
    const float* b_hh  = (const float*)d_in[4];
    const float* W_lin = (const float*)d_in[5];
    const float* b_lin = (const float*)d_in[6];
    lstm_seq_kernel<<<1, NTHREADS>>>(x, W_ih, W_hh, b_ih, b_hh, W_lin, b_lin,
                                     (float*)d_out);
}

// round 7
// speedup vs baseline: 1.5945x; 1.1604x over previous
#include <cuda_runtime.h>

// T=2048, B=1024, H=50, 4H=200. Only batch row B-1 reaches the output
// (reference takes hs[:, -1, :] on the batch axis) and the recurrence is
// batch-independent -> single length-2048 sequence, H=50, on ONE SM.
#define TT 2048
#define BB 1024
#define HH 50
#define GG 200
#define NTHREADS 128   // 4 warps, 1 per SMSP; lane pair 2u/2u+1 owns unit u

// Per-timestep hidden history; output dot handled in parallel epilogue.
__device__ float g_hs[TT * HH];

typedef unsigned long long ull;

__device__ __forceinline__ ull ffma2(ull a, ull b, ull c) {
    ull d;
    asm("fma.rn.f32x2 %0, %1, %2, %3;" : "=l"(d) : "l"(a), "l"(b), "l"(c));
    return d;
}

__device__ __forceinline__ float tanh_fast(float x) {
    float r;
    asm("tanh.approx.f32 %0, %1;" : "=f"(r) : "f"(x));
    return r;
}

__device__ __forceinline__ float f2lo(ull v) { union { ull u; float2 f; } w; w.u = v; return w.f.x; }
__device__ __forceinline__ float f2hi(ull v) { union { ull u; float2 f; } w; w.u = v; return w.f.y; }

__global__ __launch_bounds__(NTHREADS, 1)
void lstm_seq_kernel(const float* __restrict__ x,      // (T, B, 1)
                     const float* __restrict__ W_ih,   // (4H, 1)
                     const float* __restrict__ W_hh,   // (4H, H)
                     const float* __restrict__ b_ih,
                     const float* __restrict__ b_hh,
                     const float* __restrict__ W_lin,  // (1, H)
                     const float* __restrict__ b_lin,
                     float* __restrict__ out)          // T floats
{
    __shared__ __align__(16) float h_s[2][56];  // double buffer
    __shared__ float xcol[TT];

    const int j    = threadIdx.x;
    const int half = j & 1;                 // 0: gates (i,g)   1: gates (f,o)
    const int u    = j >> 1;                // unit 0..63 (>=50 redundant)
    const int uc   = (u < HH) ? u : (HH - 1);
    // rowA: i (even) / f (odd) -- always sigmoid
    // rowB: g (even, tanh) / o (odd, sigmoid)
    const int rowA = half ? (HH + uc)     : uc;
    const int rowB = half ? (3 * HH + uc) : (2 * HH + uc);

    for (int t = j; t < TT; t += NTHREADS) xcol[t] = x[t * BB + (BB - 1)];
    if (j < 56) { h_s[0][j] = 0.0f; h_s[1][j] = 0.0f; }

    // Two weight rows per thread, packed f32x2 (row byte offset j*200, 8B aligned)
    ull wpA[25], wpB[25];
    {
        const ull* ra = reinterpret_cast<const ull*>(W_hh + rowA * HH);
        const ull* rb = reinterpret_cast<const ull*>(W_hh + rowB * HH);
        #pragma unroll
        for (int k = 0; k < 25; k++) { wpA[k] = ra[k]; wpB[k] = rb[k]; }
    }
    const float bsumA = b_ih[rowA] + b_hh[rowA];
    const float bsumB = b_ih[rowB] + b_hh[rowB];
    const float wihA  = W_ih[rowA];
    const float wihB  = W_ih[rowB];
    // activation constants for rowB: tanh (even) vs sigmoid (odd)
    const float ascB  = half ? 0.5f : 1.0f;
    const float amulB = half ? 0.5f : 1.0f;
    const float aaddB = half ? 0.5f : 0.0f;

    float c = 0.0f;
    __syncthreads();

    #pragma unroll 1
    for (int t2 = 0; t2 < TT; t2 += 2) {
        #pragma unroll
        for (int s = 0; s < 2; s++) {
            const int t = t2 + s;
            const float* hsrc = h_s[s];
            float*       hdst = h_s[s ^ 1];
            const float  xv   = xcol[t];
            float preA0 = fmaf(xv, wihA, bsumA);
            float preB0 = fmaf(xv, wihB, bsumB);

            // --- two 50-dots sharing one h load (13 LDS.128) ---
            ull aA0 = 0ull, aA1 = 0ull, aB0 = 0ull, aB1 = 0ull;
            const ulonglong2* h4 = reinterpret_cast<const ulonglong2*>(hsrc);
            #pragma unroll
            for (int k = 0; k < 12; k++) {
                ulonglong2 p = h4[k];
                aA0 = ffma2(wpA[2 * k],     p.x, aA0);
                aA1 = ffma2(wpA[2 * k + 1], p.y, aA1);
                aB0 = ffma2(wpB[2 * k],     p.x, aB0);
                aB1 = ffma2(wpB[2 * k + 1], p.y, aB1);
            }
            {
                ull hl = reinterpret_cast<const ull*>(hsrc)[24];
                aA0 = ffma2(wpA[24], hl, aA0);
                aB0 = ffma2(wpB[24], hl, aB0);
            }
            float preA = preA0 + ((f2lo(aA0) + f2lo(aA1)) + (f2hi(aA0) + f2hi(aA1)));
            float preB = preB0 + ((f2lo(aB0) + f2lo(aB1)) + (f2hi(aB0) + f2hi(aB1)));

            // activations: A is sigmoid; B is tanh (even) / sigmoid (odd)
            float aAv = fmaf(tanh_fast(preA * 0.5f), 0.5f, 0.5f);
            float aBv = fmaf(tanh_fast(preB * ascB), amulB, aaddB);

            // even lane: p = i*g ; odd lane: has f=aAv, o=aBv
            float pown = aAv * aBv;           // meaningful on even lane only
            float s1 = __shfl_xor_sync(0xffffffffu, half ? aAv : pown, 1, 32);
            float s2 = __shfl_xor_sync(0xffffffffu, half ? aBv : pown, 1, 32);
            // even: f=s1, o=s2, p=pown ; odd: p=s1, f=aAv, o=aBv
            float fv = half ? aAv  : s1;
            float ov = half ? aBv  : s2;
            float pv = half ? s1   : pown;

            c = fmaf(fv, c, pv);              // identical values/order both lanes
            float hn = ov * tanh_fast(c);
            if (!half && u < HH) {
                hdst[u] = hn;
                g_hs[t * HH + u] = hn;        // fire-and-forget for epilogue
            }
            __syncthreads();
        }
    }

    // Epilogue: out[t] = dot(h_t, W_lin) + b_lin, parallel over t.
    const float bl = b_lin[0];
    for (int t = j; t < TT; t += NTHREADS) {
        float s = bl;
        #pragma unroll
        for (int k = 0; k < HH; k++) s += g_hs[t * HH + k] * W_lin[k];
        out[t] = s;
    }
}

extern "C" void kernel_launch(void* const* d_in, const int* in_sizes, int n_in,
                              void* d_out, int out_size) {
    const float* x     = (const float*)d_in[0];
    const float* W_ih  = (const float*)d_in[1];
    const float* W_hh  = (const float*)d_in[2];
    const float* b_ih  = (const float*)d_in[3];
    const float* b_hh  = (const float*)d_in[4];
    const float* W_lin = (const float*)d_in[5];
    const float* b_lin = (const float*)d_in[6];
    lstm_seq_kernel<<<1, NTHREADS>>>(x, W_ih, W_hh, b_ih, b_hh, W_lin, b_lin,
                                     (float*)d_out);
}